// round 1
// baseline (speedup 1.0000x reference)
#include <cuda_runtime.h>
#include <cuda_bf16.h>
#include <math.h>

// Problem constants
#define S_LEN 2048
#define HID 2048
#define NH 16
#define NKV 4
#define HD 128
#define QKV_OUT 3072   // (16 + 2*4) * 128
#define Q_SZ 2048      // 16*128
#define KV_SZ 512      // 4*128
#define SCALE_Q 0.08838834764831845f  // 128^-0.5

// ---------------- scratch (static device arrays; no allocation) -------------
__device__ float g_qkv[S_LEN * QKV_OUT];       // 25.2 MB
__device__ float g_q[S_LEN * NH * HD];         // 16.8 MB  (pre-scaled by SCALE)
__device__ float g_k[S_LEN * NKV * HD];        // 4.2 MB
__device__ float g_v[S_LEN * NKV * HD];        // 4.2 MB
__device__ float g_attn[S_LEN * NH * HD];      // 16.8 MB

// ---------------- GEMM: C[M,N] = A[M,K] @ B[N,K]^T + bias[N] ----------------
// 128x128 tile, 256 threads, 8x8 per thread, KT=16, transposed smem tiles.
__global__ void gemm_nt_bias(const float* __restrict__ A,
                             const float* __restrict__ B,
                             const float* __restrict__ bias,
                             float* __restrict__ C,
                             int M, int N, int K) {
    __shared__ float Ast[16][129];
    __shared__ float Bst[16][129];
    const int t = threadIdx.x;
    const int tx = t & 15, ty = t >> 4;
    const int m0 = blockIdx.y * 128, n0 = blockIdx.x * 128;

    float acc[8][8];
#pragma unroll
    for (int i = 0; i < 8; i++)
#pragma unroll
        for (int j = 0; j < 8; j++) acc[i][j] = 0.f;

    for (int k0 = 0; k0 < K; k0 += 16) {
#pragma unroll
        for (int i = 0; i < 8; i++) {
            int idx = t + i * 256;      // 0..2047
            int r = idx >> 4, kk = idx & 15;
            Ast[kk][r] = A[(size_t)(m0 + r) * K + k0 + kk];
            Bst[kk][r] = B[(size_t)(n0 + r) * K + k0 + kk];
        }
        __syncthreads();
#pragma unroll
        for (int kk = 0; kk < 16; kk++) {
            float a[8], b[8];
#pragma unroll
            for (int i = 0; i < 8; i++) a[i] = Ast[kk][ty + 16 * i];
#pragma unroll
            for (int j = 0; j < 8; j++) b[j] = Bst[kk][tx + 16 * j];
#pragma unroll
            for (int i = 0; i < 8; i++)
#pragma unroll
                for (int j = 0; j < 8; j++) acc[i][j] += a[i] * b[j];
        }
        __syncthreads();
    }
#pragma unroll
    for (int i = 0; i < 8; i++) {
        int m = m0 + ty + 16 * i;
#pragma unroll
        for (int j = 0; j < 8; j++) {
            int n = n0 + tx + 16 * j;
            C[(size_t)m * N + n] = acc[i][j] + bias[n];
        }
    }
}

// ---------------- copy caches into scratch ----------------------------------
__global__ void copy_caches(const float* __restrict__ kc, const float* __restrict__ vc) {
    int n = S_LEN * NKV * HD;
    for (int i = blockIdx.x * blockDim.x + threadIdx.x; i < n; i += gridDim.x * blockDim.x) {
        g_k[i] = kc[i];
        g_v[i] = vc[i];
    }
}

// ---------------- fused RMSNorm + RoPE + scale + scatter ---------------------
// grid = (S, 24), 128 threads. head 0..15 -> Q, 16..19 -> K, 20..23 -> V.
__global__ void norm_rope_scatter(const float* __restrict__ cosb,
                                  const float* __restrict__ sinb,
                                  const float* __restrict__ qw,
                                  const float* __restrict__ kw,
                                  const int* __restrict__ widx) {
    const int s = blockIdx.x;
    const int head = blockIdx.y;
    const int d = threadIdx.x;
    __shared__ float sh[128];
    __shared__ float wsum[4];

    int col;
    if (head < 16)      col = head * HD + d;
    else if (head < 20) col = Q_SZ + (head - 16) * HD + d;
    else                col = Q_SZ + KV_SZ + (head - 20) * HD + d;

    float x = g_qkv[(size_t)s * QKV_OUT + col];

    if (head >= 20) {  // V: plain scatter (uniform branch per block)
        int idx = widx[s];
        g_v[((size_t)idx * NKV + (head - 20)) * HD + d] = x;
        return;
    }

    // RMS norm over 128 elems
    float sq = x * x;
#pragma unroll
    for (int m = 16; m; m >>= 1) sq += __shfl_xor_sync(0xffffffffu, sq, m);
    if ((d & 31) == 0) wsum[d >> 5] = sq;
    __syncthreads();
    float ms = (wsum[0] + wsum[1] + wsum[2] + wsum[3]) * (1.0f / 128.0f);
    float inv = rsqrtf(ms + 1e-6f);
    const float* w = (head < 16) ? qw : kw;
    float y = x * inv * w[d];
    sh[d] = y;
    __syncthreads();

    if (d < 64) {
        float c = cosb[s * 64 + d], sn = sinb[s * 64 + d];
        float x1 = sh[d], x2 = sh[d + 64];
        float y1 = x1 * c - x2 * sn;
        float y2 = x1 * sn + x2 * c;
        if (head < 16) {
            float* dst = g_q + ((size_t)s * NH + head) * HD;
            dst[d] = y1 * SCALE_Q;
            dst[d + 64] = y2 * SCALE_Q;
        } else {
            int idx = widx[s];
            float* dst = g_k + ((size_t)idx * NKV + (head - 16)) * HD;
            dst[d] = y1;
            dst[d + 64] = y2;
        }
    }
}

// ---------------- flash attention -------------------------------------------
// grid = (S/64, NH), 256 threads. Block: 64-query tile of one head.
// smem: Qt[128][65] + Kt[128][65] + Vs[64][128] + Ps[64][65] = 115968 B
#define ATTN_SMEM ((128 * 65 * 2 + 64 * 128 + 64 * 65) * 4)
__global__ void attn_kernel(const float* __restrict__ mask) {
    extern __shared__ float sm[];
    float* Qt = sm;                    // [d][r] stride 65
    float* Kt = Qt + 128 * 65;         // [d][c] stride 65
    float* Vs = Kt + 128 * 65;         // [c][d] stride 128
    float* Ps = Vs + 64 * 128;         // [r][c] stride 65

    const int t = threadIdx.x;
    const int tx = t & 15, ty = t >> 4;
    const int q0 = blockIdx.x * 64;
    const int h = blockIdx.y;
    const int kvh = h >> 2;

    // load Q tile (transposed)
#pragma unroll
    for (int i = 0; i < 32; i++) {
        int idx = t + i * 256;          // 0..8191
        int d = idx & 127, r = idx >> 7;
        Qt[d * 65 + r] = g_q[((size_t)(q0 + r) * NH + h) * HD + d];
    }

    float o[4][8];
    float mrow[4], lrow[4];
#pragma unroll
    for (int i = 0; i < 4; i++) {
        mrow[i] = -1e30f; lrow[i] = 0.f;
#pragma unroll
        for (int j = 0; j < 8; j++) o[i][j] = 0.f;
    }

    const int ktiles = blockIdx.x + 1;  // causal: fully-masked tiles contribute exactly 0
    for (int kt = 0; kt < ktiles; kt++) {
        const int k0 = kt * 64;
        __syncthreads();  // previous PV done before overwriting K/V (also covers Q load)
#pragma unroll
        for (int i = 0; i < 32; i++) {
            int idx = t + i * 256;
            int d = idx & 127, c = idx >> 7;
            Kt[d * 65 + c] = g_k[((size_t)(k0 + c) * NKV + kvh) * HD + d];
            Vs[c * 128 + d] = g_v[((size_t)(k0 + c) * NKV + kvh) * HD + d];
        }
        __syncthreads();

        // scores S[64q][64k], 4x4 per thread
        float sc[4][4];
#pragma unroll
        for (int i = 0; i < 4; i++)
#pragma unroll
            for (int j = 0; j < 4; j++) sc[i][j] = 0.f;
#pragma unroll 8
        for (int d = 0; d < 128; d++) {
            float qv[4], kv[4];
#pragma unroll
            for (int i = 0; i < 4; i++) qv[i] = Qt[d * 65 + ty + 16 * i];
#pragma unroll
            for (int j = 0; j < 4; j++) kv[j] = Kt[d * 65 + tx + 16 * j];
#pragma unroll
            for (int i = 0; i < 4; i++)
#pragma unroll
                for (int j = 0; j < 4; j++) sc[i][j] += qv[i] * kv[j];
        }

        // mask + online softmax (rows r = ty+16i; reduce over the 16 tx lanes)
#pragma unroll
        for (int i = 0; i < 4; i++) {
            int r = q0 + ty + 16 * i;
            float tmax = -1e30f;
#pragma unroll
            for (int j = 0; j < 4; j++) {
                int c = k0 + tx + 16 * j;
                sc[i][j] += mask[(size_t)r * S_LEN + c];
                tmax = fmaxf(tmax, sc[i][j]);
            }
#pragma unroll
            for (int mm = 8; mm; mm >>= 1)
                tmax = fmaxf(tmax, __shfl_xor_sync(0xffffffffu, tmax, mm));
            float mnew = fmaxf(mrow[i], tmax);
            float scalef = __expf(mrow[i] - mnew);
            mrow[i] = mnew;
            float tsum = 0.f;
#pragma unroll
            for (int j = 0; j < 4; j++) {
                float p = __expf(sc[i][j] - mnew);
                sc[i][j] = p;
                tsum += p;
            }
#pragma unroll
            for (int mm = 8; mm; mm >>= 1)
                tsum += __shfl_xor_sync(0xffffffffu, tsum, mm);
            lrow[i] = lrow[i] * scalef + tsum;
#pragma unroll
            for (int j = 0; j < 8; j++) o[i][j] *= scalef;
#pragma unroll
            for (int j = 0; j < 4; j++)
                Ps[(ty + 16 * i) * 65 + tx + 16 * j] = sc[i][j];
        }
        __syncthreads();

        // O += P @ V
#pragma unroll 4
        for (int k = 0; k < 64; k++) {
            float pv[4], vv[8];
#pragma unroll
            for (int i = 0; i < 4; i++) pv[i] = Ps[(ty + 16 * i) * 65 + k];
#pragma unroll
            for (int j = 0; j < 8; j++) vv[j] = Vs[k * 128 + tx + 16 * j];
#pragma unroll
            for (int i = 0; i < 4; i++)
#pragma unroll
                for (int j = 0; j < 8; j++) o[i][j] += pv[i] * vv[j];
        }
    }

    // epilogue
#pragma unroll
    for (int i = 0; i < 4; i++) {
        float invl = 1.0f / lrow[i];
        int r = q0 + ty + 16 * i;
#pragma unroll
        for (int j = 0; j < 8; j++)
            g_attn[(size_t)r * (NH * HD) + h * HD + tx + 16 * j] = o[i][j] * invl;
    }
}

// ---------------- launch -----------------------------------------------------
extern "C" void kernel_launch(void* const* d_in, const int* in_sizes, int n_in,
                              void* d_out, int out_size) {
    const float* hidden = (const float*)d_in[0];
    const float* cosb   = (const float*)d_in[1];
    const float* sinb   = (const float*)d_in[2];
    const float* kcache = (const float*)d_in[3];
    const float* vcache = (const float*)d_in[4];
    const float* mask   = (const float*)d_in[5];
    const float* wqkv   = (const float*)d_in[6];
    const float* bqkv   = (const float*)d_in[7];
    const float* wo     = (const float*)d_in[8];
    const float* bo     = (const float*)d_in[9];
    const float* qw     = (const float*)d_in[10];
    const float* kw     = (const float*)d_in[11];
    const int*   widx   = (const int*)d_in[12];
    float* out = (float*)d_out;

    float *p_qkv, *p_attn;
    cudaGetSymbolAddress((void**)&p_qkv, g_qkv);
    cudaGetSymbolAddress((void**)&p_attn, g_attn);

    static bool attr_set = false;
    if (!attr_set) {
        cudaFuncSetAttribute(attn_kernel, cudaFuncAttributeMaxDynamicSharedMemorySize, ATTN_SMEM);
        attr_set = true;
    }

    // 1. QKV GEMM: [2048,3072] = hidden @ wqkv^T + bqkv
    gemm_nt_bias<<<dim3(QKV_OUT / 128, S_LEN / 128), 256>>>(
        hidden, wqkv, bqkv, p_qkv, S_LEN, QKV_OUT, HID);

    // 2. caches -> scratch
    copy_caches<<<256, 256>>>(kcache, vcache);

    // 3. RMSNorm + RoPE + scale + scatter
    norm_rope_scatter<<<dim3(S_LEN, 24), 128>>>(cosb, sinb, qw, kw, widx);

    // 4. flash attention
    attn_kernel<<<dim3(S_LEN / 64, NH), 256, ATTN_SMEM>>>(mask);

    // 5. output projection: [2048,2048] = attn @ wo^T + bo
    gemm_nt_bias<<<dim3(HID / 128, S_LEN / 128), 256>>>(
        p_attn, wo, bo, out, S_LEN, HID, NH * HD);
}

// round 3
// speedup vs baseline: 1.3473x; 1.3473x over previous
#include <cuda_runtime.h>
#include <cuda_bf16.h>
#include <cstdint>
#include <math.h>

// Problem constants
#define S_LEN 2048
#define HID 2048
#define NH 16
#define NKV 4
#define HD 128
#define QKV_OUT 3072   // (16 + 2*4) * 128
#define Q_SZ 2048      // 16*128
#define KV_SZ 512      // 4*128
#define SCALE_Q 0.08838834764831845f  // 128^-0.5

// ---------------- scratch (static device arrays; no allocation) -------------
__device__ float g_qkv[S_LEN * QKV_OUT];
__device__ float g_q[S_LEN * NH * HD];
__device__ float g_k[S_LEN * NKV * HD];
__device__ float g_v[S_LEN * NKV * HD];
__device__ float g_attn[S_LEN * NH * HD];

// =================== helpers =================================================
__device__ __forceinline__ float tf32_rna(float x) {
    uint32_t r;
    asm("cvt.rna.tf32.f32 %0, %1;" : "=r"(r) : "f"(x));
    return __uint_as_float(r);
}
__device__ __forceinline__ void split4(float4 v, float4& hi, float4& lo) {
    hi.x = tf32_rna(v.x); lo.x = tf32_rna(v.x - hi.x);
    hi.y = tf32_rna(v.y); lo.y = tf32_rna(v.y - hi.y);
    hi.z = tf32_rna(v.z); lo.z = tf32_rna(v.z - hi.z);
    hi.w = tf32_rna(v.w); lo.w = tf32_rna(v.w - hi.w);
}

#define MMA_TF32(d, a, b) \
    asm volatile( \
        "mma.sync.aligned.m16n8k8.row.col.f32.tf32.tf32.f32 " \
        "{%0,%1,%2,%3}, {%4,%5,%6,%7}, {%8,%9}, {%0,%1,%2,%3};" \
        : "+f"((d)[0]), "+f"((d)[1]), "+f"((d)[2]), "+f"((d)[3]) \
        : "r"((a)[0]), "r"((a)[1]), "r"((a)[2]), "r"((a)[3]), \
          "r"((b)[0]), "r"((b)[1]))

// =================== 3xTF32 mma.sync GEMM ====================================
// C[M,N] = A[M,K] @ B[N,K]^T + bias[N], fp32 in/out.
// CTA tile 128x128, 256 threads (8 warps, 4x2), warp tile 32x64, K-chunk 32.
// smem per stage: Ahi|Alo|Bhi|Blo, each [128][36] floats (skewed, conflict-free)
#define GPAD 36
#define GBUF (128 * GPAD)                    // floats per buffer = 4608
#define G_STAGE_FLOATS (4 * GBUF)            // 18432 floats
#define G_SMEM_BYTES (2 * G_STAGE_FLOATS * 4) // 147456 B

__global__ void __launch_bounds__(256, 1)
gemm_tc(const float* __restrict__ A, const float* __restrict__ B,
        const float* __restrict__ bias, float* __restrict__ C,
        int N, int K) {
    extern __shared__ float smem[];
    const int t = threadIdx.x;
    const int lane = t & 31, wid = t >> 5;
    const int g = lane >> 2, tg = lane & 3;
    const int wm = (wid & 3) * 32;   // warp m offset in tile
    const int wn = (wid >> 2) * 64;  // warp n offset in tile
    const int m0 = blockIdx.y << 7, n0 = blockIdx.x << 7;
    const int nch = K >> 5;

    float d[2][8][4];
#pragma unroll
    for (int i = 0; i < 2; i++)
#pragma unroll
        for (int j = 0; j < 8; j++)
#pragma unroll
            for (int q = 0; q < 4; q++) d[i][j][q] = 0.f;

    float4 ra[4], rb[4];

#define G_LOADC(c) do { \
    _Pragma("unroll") \
    for (int i = 0; i < 4; i++) { \
        int idx = t + (i << 8); int r = idx >> 3, q = idx & 7; \
        ra[i] = *(const float4*)(A + (size_t)(m0 + r) * K + ((c) << 5) + (q << 2)); \
        rb[i] = *(const float4*)(B + (size_t)(n0 + r) * K + ((c) << 5) + (q << 2)); \
    } } while (0)

#define G_STSC(st) do { \
    float* Ah = smem + (st) * G_STAGE_FLOATS; \
    float* Al = Ah + GBUF; \
    float* Bh = Al + GBUF; \
    float* Bl = Bh + GBUF; \
    _Pragma("unroll") \
    for (int i = 0; i < 4; i++) { \
        int idx = t + (i << 8); int r = idx >> 3, q = idx & 7; \
        int off = r * GPAD + (q << 2); \
        float4 hi, lo; \
        split4(ra[i], hi, lo); \
        *(float4*)(Ah + off) = hi; \
        *(float4*)(Al + off) = lo; \
        split4(rb[i], hi, lo); \
        *(float4*)(Bh + off) = hi; \
        *(float4*)(Bl + off) = lo; \
    } } while (0)

    G_LOADC(0);
    G_STSC(0);
    __syncthreads();

    for (int c = 0; c < nch; c++) {
        const int st = c & 1;
        if (c + 1 < nch) G_LOADC(c + 1);

        const uint32_t* Ah = (const uint32_t*)(smem + st * G_STAGE_FLOATS);
        const uint32_t* Al = Ah + GBUF;
        const uint32_t* Bh = Al + GBUF;
        const uint32_t* Bl = Bh + GBUF;

#pragma unroll
        for (int ks = 0; ks < 4; ks++) {
            const int kb = ks * 8;
            uint32_t ah[2][4], al[2][4];
#pragma unroll
            for (int i = 0; i < 2; i++) {
                int r0 = wm + i * 16 + g;
                ah[i][0] = Ah[r0 * GPAD + kb + tg];
                ah[i][1] = Ah[(r0 + 8) * GPAD + kb + tg];
                ah[i][2] = Ah[r0 * GPAD + kb + tg + 4];
                ah[i][3] = Ah[(r0 + 8) * GPAD + kb + tg + 4];
                al[i][0] = Al[r0 * GPAD + kb + tg];
                al[i][1] = Al[(r0 + 8) * GPAD + kb + tg];
                al[i][2] = Al[r0 * GPAD + kb + tg + 4];
                al[i][3] = Al[(r0 + 8) * GPAD + kb + tg + 4];
            }
            uint32_t bh[8][2], bl[8][2];
#pragma unroll
            for (int j = 0; j < 8; j++) {
                int n = wn + j * 8 + g;
                bh[j][0] = Bh[n * GPAD + kb + tg];
                bh[j][1] = Bh[n * GPAD + kb + tg + 4];
                bl[j][0] = Bl[n * GPAD + kb + tg];
                bl[j][1] = Bl[n * GPAD + kb + tg + 4];
            }
#pragma unroll
            for (int i = 0; i < 2; i++)
#pragma unroll
                for (int j = 0; j < 8; j++) {
                    MMA_TF32(d[i][j], ah[i], bh[j]);
                    MMA_TF32(d[i][j], ah[i], bl[j]);
                    MMA_TF32(d[i][j], al[i], bh[j]);
                }
        }

        if (c + 1 < nch) {
            __syncthreads();
            G_STSC(st ^ 1);
            __syncthreads();
        }
    }

    // epilogue: bias + store (float2 per fragment half)
#pragma unroll
    for (int i = 0; i < 2; i++) {
        int r = m0 + wm + i * 16 + g;
#pragma unroll
        for (int j = 0; j < 8; j++) {
            int cix = n0 + wn + j * 8 + tg * 2;
            float2 b2 = *(const float2*)(bias + cix);
            float2 v0, v1;
            v0.x = d[i][j][0] + b2.x; v0.y = d[i][j][1] + b2.y;
            v1.x = d[i][j][2] + b2.x; v1.y = d[i][j][3] + b2.y;
            *(float2*)(C + (size_t)r * N + cix) = v0;
            *(float2*)(C + (size_t)(r + 8) * N + cix) = v1;
        }
    }
#undef G_LOADC
#undef G_STSC
}

// ---------------- copy caches into scratch ----------------------------------
__global__ void copy_caches(const float* __restrict__ kc, const float* __restrict__ vc) {
    int n = S_LEN * NKV * HD;
    for (int i = blockIdx.x * blockDim.x + threadIdx.x; i < n; i += gridDim.x * blockDim.x) {
        g_k[i] = kc[i];
        g_v[i] = vc[i];
    }
}

// ---------------- fused RMSNorm + RoPE + scale + scatter ---------------------
__global__ void norm_rope_scatter(const float* __restrict__ cosb,
                                  const float* __restrict__ sinb,
                                  const float* __restrict__ qw,
                                  const float* __restrict__ kw,
                                  const int* __restrict__ widx) {
    const int s = blockIdx.x;
    const int head = blockIdx.y;
    const int d = threadIdx.x;
    __shared__ float sh[128];
    __shared__ float wsum[4];

    int col;
    if (head < 16)      col = head * HD + d;
    else if (head < 20) col = Q_SZ + (head - 16) * HD + d;
    else                col = Q_SZ + KV_SZ + (head - 20) * HD + d;

    float x = g_qkv[(size_t)s * QKV_OUT + col];

    if (head >= 20) {
        int idx = widx[s];
        g_v[((size_t)idx * NKV + (head - 20)) * HD + d] = x;
        return;
    }

    float sq = x * x;
#pragma unroll
    for (int m = 16; m; m >>= 1) sq += __shfl_xor_sync(0xffffffffu, sq, m);
    if ((d & 31) == 0) wsum[d >> 5] = sq;
    __syncthreads();
    float ms = (wsum[0] + wsum[1] + wsum[2] + wsum[3]) * (1.0f / 128.0f);
    float inv = rsqrtf(ms + 1e-6f);
    const float* w = (head < 16) ? qw : kw;
    float y = x * inv * w[d];
    sh[d] = y;
    __syncthreads();

    if (d < 64) {
        float c = cosb[s * 64 + d], sn = sinb[s * 64 + d];
        float x1 = sh[d], x2 = sh[d + 64];
        float y1 = x1 * c - x2 * sn;
        float y2 = x1 * sn + x2 * c;
        if (head < 16) {
            float* dst = g_q + ((size_t)s * NH + head) * HD;
            dst[d] = y1 * SCALE_Q;
            dst[d + 64] = y2 * SCALE_Q;
        } else {
            int idx = widx[s];
            float* dst = g_k + ((size_t)idx * NKV + (head - 16)) * HD;
            dst[d] = y1;
            dst[d + 64] = y2;
        }
    }
}

// ---------------- flash attention (unchanged) --------------------------------
#define ATTN_SMEM ((128 * 65 * 2 + 64 * 128 + 64 * 65) * 4)
__global__ void attn_kernel(const float* __restrict__ mask) {
    extern __shared__ float sm[];
    float* Qt = sm;
    float* Kt = Qt + 128 * 65;
    float* Vs = Kt + 128 * 65;
    float* Ps = Vs + 64 * 128;

    const int t = threadIdx.x;
    const int tx = t & 15, ty = t >> 4;
    const int q0 = blockIdx.x * 64;
    const int h = blockIdx.y;
    const int kvh = h >> 2;

#pragma unroll
    for (int i = 0; i < 32; i++) {
        int idx = t + i * 256;
        int d = idx & 127, r = idx >> 7;
        Qt[d * 65 + r] = g_q[((size_t)(q0 + r) * NH + h) * HD + d];
    }

    float o[4][8];
    float mrow[4], lrow[4];
#pragma unroll
    for (int i = 0; i < 4; i++) {
        mrow[i] = -1e30f; lrow[i] = 0.f;
#pragma unroll
        for (int j = 0; j < 8; j++) o[i][j] = 0.f;
    }

    const int ktiles = blockIdx.x + 1;
    for (int kt = 0; kt < ktiles; kt++) {
        const int k0 = kt * 64;
        __syncthreads();
#pragma unroll
        for (int i = 0; i < 32; i++) {
            int idx = t + i * 256;
            int d = idx & 127, c = idx >> 7;
            Kt[d * 65 + c] = g_k[((size_t)(k0 + c) * NKV + kvh) * HD + d];
            Vs[c * 128 + d] = g_v[((size_t)(k0 + c) * NKV + kvh) * HD + d];
        }
        __syncthreads();

        float sc[4][4];
#pragma unroll
        for (int i = 0; i < 4; i++)
#pragma unroll
            for (int j = 0; j < 4; j++) sc[i][j] = 0.f;
#pragma unroll 8
        for (int d = 0; d < 128; d++) {
            float qv[4], kv[4];
#pragma unroll
            for (int i = 0; i < 4; i++) qv[i] = Qt[d * 65 + ty + 16 * i];
#pragma unroll
            for (int j = 0; j < 4; j++) kv[j] = Kt[d * 65 + tx + 16 * j];
#pragma unroll
            for (int i = 0; i < 4; i++)
#pragma unroll
                for (int j = 0; j < 4; j++) sc[i][j] += qv[i] * kv[j];
        }

#pragma unroll
        for (int i = 0; i < 4; i++) {
            int r = q0 + ty + 16 * i;
            float tmax = -1e30f;
#pragma unroll
            for (int j = 0; j < 4; j++) {
                int c = k0 + tx + 16 * j;
                sc[i][j] += mask[(size_t)r * S_LEN + c];
                tmax = fmaxf(tmax, sc[i][j]);
            }
#pragma unroll
            for (int mm = 8; mm; mm >>= 1)
                tmax = fmaxf(tmax, __shfl_xor_sync(0xffffffffu, tmax, mm));
            float mnew = fmaxf(mrow[i], tmax);
            float scalef = __expf(mrow[i] - mnew);
            mrow[i] = mnew;
            float tsum = 0.f;
#pragma unroll
            for (int j = 0; j < 4; j++) {
                float p = __expf(sc[i][j] - mnew);
                sc[i][j] = p;
                tsum += p;
            }
#pragma unroll
            for (int mm = 8; mm; mm >>= 1)
                tsum += __shfl_xor_sync(0xffffffffu, tsum, mm);
            lrow[i] = lrow[i] * scalef + tsum;
#pragma unroll
            for (int j = 0; j < 8; j++) o[i][j] *= scalef;
#pragma unroll
            for (int j = 0; j < 4; j++)
                Ps[(ty + 16 * i) * 65 + tx + 16 * j] = sc[i][j];
        }
        __syncthreads();

#pragma unroll 4
        for (int k = 0; k < 64; k++) {
            float pv[4], vv[8];
#pragma unroll
            for (int i = 0; i < 4; i++) pv[i] = Ps[(ty + 16 * i) * 65 + k];
#pragma unroll
            for (int j = 0; j < 8; j++) vv[j] = Vs[k * 128 + tx + 16 * j];
#pragma unroll
            for (int i = 0; i < 4; i++)
#pragma unroll
                for (int j = 0; j < 8; j++) o[i][j] += pv[i] * vv[j];
        }
    }

#pragma unroll
    for (int i = 0; i < 4; i++) {
        float invl = 1.0f / lrow[i];
        int r = q0 + ty + 16 * i;
#pragma unroll
        for (int j = 0; j < 8; j++)
            g_attn[(size_t)r * (NH * HD) + h * HD + tx + 16 * j] = o[i][j] * invl;
    }
}

// ---------------- launch -----------------------------------------------------
extern "C" void kernel_launch(void* const* d_in, const int* in_sizes, int n_in,
                              void* d_out, int out_size) {
    const float* hidden = (const float*)d_in[0];
    const float* cosb   = (const float*)d_in[1];
    const float* sinb   = (const float*)d_in[2];
    const float* kcache = (const float*)d_in[3];
    const float* vcache = (const float*)d_in[4];
    const float* mask   = (const float*)d_in[5];
    const float* wqkv   = (const float*)d_in[6];
    const float* bqkv   = (const float*)d_in[7];
    const float* wo     = (const float*)d_in[8];
    const float* bo     = (const float*)d_in[9];
    const float* qw     = (const float*)d_in[10];
    const float* kw     = (const float*)d_in[11];
    const int*   widx   = (const int*)d_in[12];
    float* out = (float*)d_out;

    float *p_qkv, *p_attn;
    cudaGetSymbolAddress((void**)&p_qkv, g_qkv);
    cudaGetSymbolAddress((void**)&p_attn, g_attn);

    static bool attr_set = false;
    if (!attr_set) {
        cudaFuncSetAttribute(attn_kernel, cudaFuncAttributeMaxDynamicSharedMemorySize, ATTN_SMEM);
        cudaFuncSetAttribute(gemm_tc, cudaFuncAttributeMaxDynamicSharedMemorySize, G_SMEM_BYTES);
        attr_set = true;
    }

    // 1. QKV GEMM: [2048,3072] = hidden @ wqkv^T + bqkv  (3xTF32 mma.sync)
    gemm_tc<<<dim3(QKV_OUT / 128, S_LEN / 128), 256, G_SMEM_BYTES>>>(
        hidden, wqkv, bqkv, p_qkv, QKV_OUT, HID);

    // 2. caches -> scratch
    copy_caches<<<256, 256>>>(kcache, vcache);

    // 3. RMSNorm + RoPE + scale + scatter
    norm_rope_scatter<<<dim3(S_LEN, 24), 128>>>(cosb, sinb, qw, kw, widx);

    // 4. flash attention
    attn_kernel<<<dim3(S_LEN / 64, NH), 256, ATTN_SMEM>>>(mask);

    // 5. output projection: [2048,2048] = attn @ wo^T + bo  (3xTF32 mma.sync)
    gemm_tc<<<dim3(HID / 128, S_LEN / 128), 256, G_SMEM_BYTES>>>(
        p_attn, wo, bo, out, HID, NH * HD);
}